// round 10
// baseline (speedup 1.0000x reference)
#include <cuda_runtime.h>
#include <cuda_fp16.h>
#include <cstdint>

#define NN 1024
#define FF 128

// Scratch (allocation-free rule: __device__ globals)
__device__ float    g_P[NN * FF];      // input @ weight                         [j,g]
__device__ unsigned g_U[NN * 256];     // fp16 (u1,u2),(u3,u4) per f -> K=512    [j,k]
__device__ unsigned g_V[NN * 256];     // fp16 (b,b^2),(b^3,b^4) per f           [i,k]
__device__ float    g_rowU[NN];        // sum_f (c1 a + c3 a^3 + c5 a^5)         [j]
__device__ float    g_rowV[NN];        // sum_f  c5 b^5                          [i]

// sigmoid(x) = 0.5 + c1 x + c3 x^3 + c5 x^5  (|x| <~ 1)
#define C1 0.25f
#define C3 (-0.020833333f)
#define C5 0.0020833333f

__device__ __forceinline__ uint32_t smem_u32(const void* p) {
    return (uint32_t)__cvta_generic_to_shared(p);
}
__device__ __forceinline__ void ldsm_x4(uint32_t* r, uint32_t a) {
    asm volatile("ldmatrix.sync.aligned.m8n8.x4.shared.b16 {%0,%1,%2,%3}, [%4];"
        : "=r"(r[0]), "=r"(r[1]), "=r"(r[2]), "=r"(r[3]) : "r"(a));
}
__device__ __forceinline__ void mma16816(float* d, const uint32_t* a,
                                         uint32_t b0, uint32_t b1) {
    asm volatile("mma.sync.aligned.m16n8k16.row.col.f32.f16.f16.f32 "
        "{%0,%1,%2,%3},{%4,%5,%6,%7},{%8,%9},{%0,%1,%2,%3};"
        : "+f"(d[0]), "+f"(d[1]), "+f"(d[2]), "+f"(d[3])
        : "r"(a[0]), "r"(a[1]), "r"(a[2]), "r"(a[3]), "r"(b0), "r"(b1));
}
__device__ __forceinline__ void cp_async16(uint32_t dst, const void* src) {
    asm volatile("cp.async.cg.shared.global [%0], [%1], 16;" :: "r"(dst), "l"(src));
}
__device__ __forceinline__ void cp_commit() {
    asm volatile("cp.async.commit_group;");
}

// ---------------------------------------------------------------------------
// Kernel 1: prep. grid (256, 4), block 256.
//   mat 0 (bx<64, 16 rows): a = input @ w1[:,:128]^T -> fp16 U feats, fp32 rowU
//   mat 1 (bx<64, 16 rows): b = input @ w1[:,128:]^T + b1 -> fp16 V, fp32 rowV
//   mat 2 (4 rows): P = input @ weight (fp32)
//   mat 3 (4 rows): out := bias
// mats 0/1 pipeline w1 staging: next chunk's 16 LDG issued to registers while
// the current chunk computes out of smem (load latency hidden, unlike R9).
// ---------------------------------------------------------------------------
__global__ __launch_bounds__(256) void prep_kernel(
        const float* __restrict__ input,
        const float* __restrict__ w1,
        const float* __restrict__ b1,
        const float* __restrict__ weight,
        const float* __restrict__ bias,
        float* __restrict__ out)
{
    const int mat = blockIdx.y;
    const int t   = threadIdx.x;
    const int col = t & 127;
    const int rh  = t >> 7;          // 0..1

    if (mat == 3) {
        const int j0 = blockIdx.x * 4;
        const float bv = bias[col];
        out[(j0 + rh * 2 + 0) * FF + col] = bv;
        out[(j0 + rh * 2 + 1) * FF + col] = bv;
        return;
    }

    if (mat < 2) {
        if (blockIdx.x >= 64) return;
        const int j0 = blockIdx.x * 16;       // 16 rows/block

        __shared__ float in_s[16][FF];        // 8 KB
        __shared__ float w_s[32][133];        // 17 KB (chunk of 32 k)
        __shared__ float red[16][4];

        for (int idx = t; idx < 16 * FF; idx += 256)
            in_s[idx >> 7][idx & 127] = input[(j0 + (idx >> 7)) * FF + (idx & 127)];

        float acc[8];
        #pragma unroll
        for (int r = 0; r < 8; r++) acc[r] = 0.f;

        const int off = mat ? 128 : 0;
        const int lk = t & 31, lf = t >> 5;   // chunk load map: idx = t + i*256
        float pre[16];
        #pragma unroll
        for (int i = 0; i < 16; i++)          // prefetch chunk 0
            pre[i] = w1[(lf + i * 8) * 256 + off + lk];

        for (int ch = 0; ch < 4; ch++) {
            #pragma unroll
            for (int i = 0; i < 16; i++)
                w_s[lk][lf + i * 8] = pre[i];
            __syncthreads();
            if (ch < 3) {
                #pragma unroll
                for (int i = 0; i < 16; i++)  // prefetch next chunk (hidden)
                    pre[i] = w1[(lf + i * 8) * 256 + off + (ch + 1) * 32 + lk];
            }
            const int k0 = ch * 32;
            #pragma unroll
            for (int k4 = 0; k4 < 8; k4++) {
                const int k = k4 * 4;
                float w0 = w_s[k + 0][col];
                float w1v = w_s[k + 1][col];
                float w2 = w_s[k + 2][col];
                float w3 = w_s[k + 3][col];
                #pragma unroll
                for (int r = 0; r < 8; r++) {
                    float4 iv = *(const float4*)&in_s[rh * 8 + r][k0 + k];
                    acc[r] += iv.x * w0;
                    acc[r] += iv.y * w1v;
                    acc[r] += iv.z * w2;
                    acc[r] += iv.w * w3;
                }
            }
            __syncthreads();   // compute done before next chunk's STS
        }

        float rsum[8];
        if (mat == 0) {
            #pragma unroll
            for (int r = 0; r < 8; r++) {
                float a = acc[r], a2 = a * a, a4 = a2 * a2;
                float u1 = C1 + 3.f * C3 * a2 + 5.f * C5 * a4;
                float u2 = a * (3.f * C3 + 10.f * C5 * a2);
                float u3 = C3 + 10.f * C5 * a2;
                float u4 = 5.f * C5 * a;
                rsum[r] = a * (C1 + a2 * (C3 + C5 * a2));   // rowU term
                __half2 h01 = __floats2half2_rn(u1, u2);
                __half2 h23 = __floats2half2_rn(u3, u4);
                *(uint2*)&g_U[(j0 + rh * 8 + r) * 256 + col * 2] =
                    make_uint2(*(unsigned*)&h01, *(unsigned*)&h23);
            }
        } else {
            const float bb = b1[col];
            #pragma unroll
            for (int r = 0; r < 8; r++) {
                float b = acc[r] + bb;
                float b2 = b * b;
                rsum[r] = C5 * b * b2 * b2;                 // rowV term (b^5)
                __half2 h01 = __floats2half2_rn(b, b2);
                __half2 h23 = __floats2half2_rn(b * b2, b2 * b2);
                *(uint2*)&g_V[(j0 + rh * 8 + r) * 256 + col * 2] =
                    make_uint2(*(unsigned*)&h01, *(unsigned*)&h23);
            }
        }
        // reduce rsum over f
        #pragma unroll
        for (int r = 0; r < 8; r++)
            #pragma unroll
            for (int o = 16; o; o >>= 1)
                rsum[r] += __shfl_xor_sync(0xffffffffu, rsum[r], o);
        if ((t & 31) == 0) {
            const int w = t >> 5;                 // rh = w>>2, col group = w&3
            #pragma unroll
            for (int r = 0; r < 8; r++)
                red[(w >> 2) * 8 + r][w & 3] = rsum[r];
        }
        __syncthreads();
        if (t < 16) {
            float v = red[t][0] + red[t][1] + red[t][2] + red[t][3];
            if (mat == 0) g_rowU[j0 + t] = v; else g_rowV[j0 + t] = v;
        }
        return;
    }

    // mat == 2: P = input @ weight, 4 rows/block, sync-free weight reads
    {
        const int j0 = blockIdx.x * 4;
        __shared__ float in_s[4][FF];
        for (int idx = t; idx < 4 * FF; idx += 256)
            in_s[idx >> 7][idx & 127] = input[(j0 + (idx >> 7)) * FF + (idx & 127)];
        __syncthreads();

        float acc[2] = {0.f, 0.f};
        #pragma unroll 4
        for (int k4 = 0; k4 < 32; k4++) {
            const int k = k4 * 4;
            float w0 = weight[(k + 0) * FF + col];
            float w1v = weight[(k + 1) * FF + col];
            float w2 = weight[(k + 2) * FF + col];
            float w3 = weight[(k + 3) * FF + col];
            #pragma unroll
            for (int r = 0; r < 2; r++) {
                float4 iv = *(const float4*)&in_s[rh * 2 + r][k];
                acc[r] += iv.x * w0;
                acc[r] += iv.y * w1v;
                acc[r] += iv.z * w2;
                acc[r] += iv.w * w3;
            }
        }
        #pragma unroll
        for (int r = 0; r < 2; r++)
            g_P[(j0 + rh * 2 + r) * FF + col] = acc[r];
    }
}

// ---------------------------------------------------------------------------
// Kernel 2: gate via HMMA + fused out GEMM.  512 threads (16 warps, 4x4 warp
// grid, warp tile 16m x 16n), cp.async double-buffered K-chunks of 32 halfs.
// smem cut 36.9 -> 20 KB so 3 blocks/SM co-reside (R9's occupancy cap was
// SMEM, not registers).
//   D[i,j]  = sum_k V[i,k] * U[j,k]                 (K = 512 halfs)
//   S[i,j]  = adj[i,j] * (64 + rowU[j] + rowV[i] + D[i,j])
//   out    += S_tile[64,64] @ P[64,128]             (atomicAdd, out = bias)
// Buffers 4 x [64][40] halfs (row = 80 B, 16B-aligned; ldmatrix bank-rotation
// conflict-free).  S_s [64][76] f32 overlay fits the same union.
// ---------------------------------------------------------------------------
__global__ __launch_bounds__(512, 3) void gate_kernel(const float* __restrict__ adj,
                                                      float* __restrict__ out)
{
    __shared__ __align__(16) char buf[4 * 64 * 40 * 2];   // 20480 B

    __half* base = (__half*)buf;          // U0 | V0 | U1 | V1, each [64][40]
    float*  S_s  = (float*)buf;           // [64][76] overlay (19456 B)

    const int t    = threadIdx.x;
    const int lane = t & 31, warp = t >> 5;
    const int j0   = blockIdx.x * 64;     // U side (n)
    const int i0   = blockIdx.y * 64;     // V side (m)
    const int wm   = warp >> 2;           // 0..3 -> i offset 16*wm
    const int wn   = warp & 3;            // 0..3 -> j offset 16*wn

    const __half* gU = (const __half*)g_U;
    const __half* gV = (const __half*)g_V;

    // loader: t<256 -> U, t>=256 -> V; one cp.async16 per thread per chunk
    const int lm   = t >> 8;              // 0 = U, 1 = V
    const int li   = t & 255;
    const int lrow = li >> 2;             // 0..63
    const int lseg = li & 3;              // 0..3 (x8 halfs)

    float d[2][4];
    #pragma unroll
    for (int n = 0; n < 2; n++)
        #pragma unroll
        for (int q = 0; q < 4; q++) d[n][q] = 0.f;

    const uint32_t sBase = smem_u32(base);
    const uint32_t BUFB  = 64 * 40 * 2;   // 5120 B per buffer
    const uint32_t ldOff = (uint32_t)(lrow * 40 + lseg * 8) * 2 + lm * BUFB;

    // ldmatrix lane base addresses (bytes) within a buffer; +ks*32 per k16
    const uint32_t aOff = (uint32_t)((16 * wm + (lane & 15)) * 40 + (lane >> 4) * 8) * 2;
    const uint32_t bOff = (uint32_t)((16 * wn + (lane & 15)) * 40 + (lane >> 4) * 8) * 2;

    const __half* src = (lm ? gV + (i0 + lrow) * 512
                            : gU + (j0 + lrow) * 512) + lseg * 8;

    // prologue: chunk 0 -> buffer pair 0
    cp_async16(sBase + ldOff, src);
    cp_commit();

    for (int ch = 0; ch < 16; ch++) {
        const int cur = ch & 1;
        if (ch < 15) {   // next chunk into the other buffer pair
            cp_async16(sBase + (cur ^ 1) * 2 * BUFB + ldOff, src + (ch + 1) * 32);
            cp_commit();
            asm volatile("cp.async.wait_group 1;");
        } else {
            asm volatile("cp.async.wait_group 0;");
        }
        __syncthreads();

        const uint32_t uB = sBase + (cur * 2 + 0) * BUFB;
        const uint32_t vB = sBase + (cur * 2 + 1) * BUFB;
        #pragma unroll
        for (int ks = 0; ks < 2; ks++) {
            uint32_t a[4], b[4];
            ldsm_x4(a, vB + aOff + ks * 32);
            ldsm_x4(b, uB + bOff + ks * 32);   // non-trans: [n][k] IS the B frag
            mma16816(d[0], a, b[0], b[2]);     // n cols +0..7
            mma16816(d[1], a, b[1], b[3]);     // n cols +8..15
        }
        __syncthreads();   // ldsm reads done before next cp.async / overlay
    }

    // scale epilogue: acc frag -> S_s  (stride 76: 12-bank/row rotation)
    {
        const int r0 = lane >> 2, c0 = (lane & 3) * 2;
        const int ilo = 16 * wm + r0, ihi = ilo + 8;
        const float rvl = g_rowV[i0 + ilo];
        const float rvh = g_rowV[i0 + ihi];
        #pragma unroll
        for (int n = 0; n < 2; n++) {
            const int jc = 16 * wn + 8 * n + c0;
            float2 alo = *(const float2*)&adj[(size_t)(i0 + ilo) * NN + j0 + jc];
            float2 ahi = *(const float2*)&adj[(size_t)(i0 + ihi) * NN + j0 + jc];
            float ru0 = g_rowU[j0 + jc], ru1 = g_rowU[j0 + jc + 1];
            S_s[ilo * 76 + jc    ] = alo.x * (64.f + ru0 + rvl + d[n][0]);
            S_s[ilo * 76 + jc + 1] = alo.y * (64.f + ru1 + rvl + d[n][1]);
            S_s[ihi * 76 + jc    ] = ahi.x * (64.f + ru0 + rvh + d[n][2]);
            S_s[ihi * 76 + jc + 1] = ahi.y * (64.f + ru1 + rvh + d[n][3]);
        }
    }
    __syncthreads();

    // out epilogue: out[i0:i0+64, :] += S_s @ P[j0:j0+64, :]
    const int g = t & 127;
    const int q = t >> 7;                 // 0..3 -> i rows q*16 .. q*16+15
    float acc[16];
    #pragma unroll
    for (int r = 0; r < 16; r++) acc[r] = 0.f;

    #pragma unroll 2
    for (int j4 = 0; j4 < 16; j4++) {
        const int jj = j4 * 4;
        const float p0 = g_P[(j0 + jj + 0) * FF + g];
        const float p1 = g_P[(j0 + jj + 1) * FF + g];
        const float p2 = g_P[(j0 + jj + 2) * FF + g];
        const float p3 = g_P[(j0 + jj + 3) * FF + g];
        #pragma unroll
        for (int r = 0; r < 16; r++) {
            float4 sv = *(const float4*)&S_s[(q * 16 + r) * 76 + jj];  // broadcast
            acc[r] += sv.x * p0;
            acc[r] += sv.y * p1;
            acc[r] += sv.z * p2;
            acc[r] += sv.w * p3;
        }
    }
    #pragma unroll
    for (int r = 0; r < 16; r++)
        atomicAdd(&out[(i0 + q * 16 + r) * FF + g], acc[r]);
}

// ---------------------------------------------------------------------------
extern "C" void kernel_launch(void* const* d_in, const int* in_sizes, int n_in,
                              void* d_out, int out_size)
{
    const float* input   = (const float*)d_in[0];   // [1024,128]
    const float* adj     = (const float*)d_in[1];   // [1024,1024]
    // d_in[2] = feat_adj : unused by the reference
    const float* weight  = (const float*)d_in[3];   // [128,128]
    const float* bias    = (const float*)d_in[4];   // [128]
    const float* w1      = (const float*)d_in[5];   // [128,256]
    const float* b1      = (const float*)d_in[6];   // [128]
    float* out = (float*)d_out;                     // [1024,128]

    prep_kernel<<<dim3(256, 4), 256>>>(input, w1, b1, weight, bias, out);
    gate_kernel<<<dim3(16, 16), 512>>>(adj, out);
}

// round 11
// speedup vs baseline: 1.2664x; 1.2664x over previous
#include <cuda_runtime.h>
#include <cuda_fp16.h>
#include <cstdint>

#define NN 1024
#define FF 128

// Scratch (allocation-free rule: __device__ globals)
__device__ unsigned g_U[NN * 256];       // fp16 (u1,u2),(u3,u4) per f -> K=512  [j,k]
__device__ unsigned g_V[NN * 256];       // fp16 (b,b^2),(b^3,b^4) per f         [i,k]
__device__ float    g_rowU[NN];          // sum_f (c1 a + c3 a^3 + c5 a^5)       [j]
__device__ float    g_rowV[NN];          // sum_f  c5 b^5                        [i]
__device__ uint4    g_PTh[FF * NN / 8];  // fp16 hi of P^T   [g][j]  (128 x 1024)
__device__ uint4    g_PTl[FF * NN / 8];  // fp16 lo residual [g][j]

// sigmoid(x) = 0.5 + c1 x + c3 x^3 + c5 x^5  (|x| <~ 1)
#define C1 0.25f
#define C3 (-0.020833333f)
#define C5 0.0020833333f

__device__ __forceinline__ uint32_t smem_u32(const void* p) {
    return (uint32_t)__cvta_generic_to_shared(p);
}
__device__ __forceinline__ void ldsm_x4(uint32_t* r, uint32_t a) {
    asm volatile("ldmatrix.sync.aligned.m8n8.x4.shared.b16 {%0,%1,%2,%3}, [%4];"
        : "=r"(r[0]), "=r"(r[1]), "=r"(r[2]), "=r"(r[3]) : "r"(a));
}
__device__ __forceinline__ void mma16816(float* d, const uint32_t* a,
                                         uint32_t b0, uint32_t b1) {
    asm volatile("mma.sync.aligned.m16n8k16.row.col.f32.f16.f16.f32 "
        "{%0,%1,%2,%3},{%4,%5,%6,%7},{%8,%9},{%0,%1,%2,%3};"
        : "+f"(d[0]), "+f"(d[1]), "+f"(d[2]), "+f"(d[3])
        : "r"(a[0]), "r"(a[1]), "r"(a[2]), "r"(a[3]), "r"(b0), "r"(b1));
}
__device__ __forceinline__ void cp_async16(uint32_t dst, const void* src) {
    asm volatile("cp.async.cg.shared.global [%0], [%1], 16;" :: "r"(dst), "l"(src));
}
__device__ __forceinline__ void cp_commit() {
    asm volatile("cp.async.commit_group;");
}

// ---------------------------------------------------------------------------
// Kernel 1: prep. grid (256, 4), block 256.
//   mat 0 (bx<64, 16 rows): a = input @ w1[:,:128]^T -> fp16 U feats, fp32 rowU
//   mat 1 (bx<64, 16 rows): b = input @ w1[:,128:]^T + b1 -> fp16 V, fp32 rowV
//   mat 2 (bx<64, 16 rows): P = input @ weight -> TRANSPOSED split-fp16 PT hi/lo
//   mat 3 (4 rows): out := bias
// ---------------------------------------------------------------------------
__global__ __launch_bounds__(256) void prep_kernel(
        const float* __restrict__ input,
        const float* __restrict__ w1,
        const float* __restrict__ b1,
        const float* __restrict__ weight,
        const float* __restrict__ bias,
        float* __restrict__ out)
{
    const int mat = blockIdx.y;
    const int t   = threadIdx.x;
    const int col = t & 127;
    const int rh  = t >> 7;          // 0..1

    if (mat == 3) {
        const int j0 = blockIdx.x * 4;
        const float bv = bias[col];
        out[(j0 + rh * 2 + 0) * FF + col] = bv;
        out[(j0 + rh * 2 + 1) * FF + col] = bv;
        return;
    }
    if (blockIdx.x >= 64) return;
    const int j0 = blockIdx.x * 16;       // 16 rows/block

    __shared__ float in_s[16][FF];        // 8 KB
    __shared__ float w_s[32][133];        // 17 KB (w1 chunk / P-transpose stage)
    __shared__ float red[16][4];

    for (int idx = t; idx < 16 * FF; idx += 256)
        in_s[idx >> 7][idx & 127] = input[(j0 + (idx >> 7)) * FF + (idx & 127)];

    float acc[8];
    #pragma unroll
    for (int r = 0; r < 8; r++) acc[r] = 0.f;

    if (mat < 2) {
        const int off = mat ? 128 : 0;
        const int lk = t & 31, lf = t >> 5;   // chunk load map
        float pre[16];
        #pragma unroll
        for (int i = 0; i < 16; i++)          // prefetch chunk 0
            pre[i] = w1[(lf + i * 8) * 256 + off + lk];

        for (int ch = 0; ch < 4; ch++) {
            #pragma unroll
            for (int i = 0; i < 16; i++)
                w_s[lk][lf + i * 8] = pre[i];
            __syncthreads();
            if (ch < 3) {
                #pragma unroll
                for (int i = 0; i < 16; i++)  // prefetch next chunk (hidden)
                    pre[i] = w1[(lf + i * 8) * 256 + off + (ch + 1) * 32 + lk];
            }
            const int k0 = ch * 32;
            #pragma unroll
            for (int k4 = 0; k4 < 8; k4++) {
                const int k = k4 * 4;
                float w0 = w_s[k + 0][col];
                float w1v = w_s[k + 1][col];
                float w2 = w_s[k + 2][col];
                float w3 = w_s[k + 3][col];
                #pragma unroll
                for (int r = 0; r < 8; r++) {
                    float4 iv = *(const float4*)&in_s[rh * 8 + r][k0 + k];
                    acc[r] += iv.x * w0;
                    acc[r] += iv.y * w1v;
                    acc[r] += iv.z * w2;
                    acc[r] += iv.w * w3;
                }
            }
            __syncthreads();   // compute done before next chunk's STS
        }

        float rsum[8];
        if (mat == 0) {
            #pragma unroll
            for (int r = 0; r < 8; r++) {
                float a = acc[r], a2 = a * a, a4 = a2 * a2;
                float u1 = C1 + 3.f * C3 * a2 + 5.f * C5 * a4;
                float u2 = a * (3.f * C3 + 10.f * C5 * a2);
                float u3 = C3 + 10.f * C5 * a2;
                float u4 = 5.f * C5 * a;
                rsum[r] = a * (C1 + a2 * (C3 + C5 * a2));   // rowU term
                __half2 h01 = __floats2half2_rn(u1, u2);
                __half2 h23 = __floats2half2_rn(u3, u4);
                *(uint2*)&g_U[(j0 + rh * 8 + r) * 256 + col * 2] =
                    make_uint2(*(unsigned*)&h01, *(unsigned*)&h23);
            }
        } else {
            const float bb = b1[col];
            #pragma unroll
            for (int r = 0; r < 8; r++) {
                float b = acc[r] + bb;
                float b2 = b * b;
                rsum[r] = C5 * b * b2 * b2;                 // rowV term (b^5)
                __half2 h01 = __floats2half2_rn(b, b2);
                __half2 h23 = __floats2half2_rn(b * b2, b2 * b2);
                *(uint2*)&g_V[(j0 + rh * 8 + r) * 256 + col * 2] =
                    make_uint2(*(unsigned*)&h01, *(unsigned*)&h23);
            }
        }
        // reduce rsum over f
        #pragma unroll
        for (int r = 0; r < 8; r++)
            #pragma unroll
            for (int o = 16; o; o >>= 1)
                rsum[r] += __shfl_xor_sync(0xffffffffu, rsum[r], o);
        if ((t & 31) == 0) {
            const int w = t >> 5;
            #pragma unroll
            for (int r = 0; r < 8; r++)
                red[(w >> 2) * 8 + r][w & 3] = rsum[r];
        }
        __syncthreads();
        if (t < 16) {
            float v = red[t][0] + red[t][1] + red[t][2] + red[t][3];
            if (mat == 0) g_rowU[j0 + t] = v; else g_rowV[j0 + t] = v;
        }
        return;
    }

    // mat == 2: P rows j0..j0+15 -> transposed split-fp16 PT[g][j]
    __syncthreads();
    #pragma unroll 4
    for (int k4 = 0; k4 < 32; k4++) {
        const int k = k4 * 4;
        float w0 = weight[(k + 0) * FF + col];
        float w1v = weight[(k + 1) * FF + col];
        float w2 = weight[(k + 2) * FF + col];
        float w3 = weight[(k + 3) * FF + col];
        #pragma unroll
        for (int r = 0; r < 8; r++) {
            float4 iv = *(const float4*)&in_s[rh * 8 + r][k];
            acc[r] += iv.x * w0;
            acc[r] += iv.y * w1v;
            acc[r] += iv.z * w2;
            acc[r] += iv.w * w3;
        }
    }
    // stage [16 j][128 g] f32 in smem, then write transposed 8-half runs
    float (*ps)[133] = (float(*)[133])w_s;    // reuse; [16][133] fits [32][133]
    #pragma unroll
    for (int r = 0; r < 8; r++) ps[rh * 8 + r][col] = acc[r];
    __syncthreads();

    {
        const int gr = t >> 1;        // 0..127 : g row
        const int jh = t & 1;         // 0..1   : j half (8 each)
        __half hi[8], lo[8];
        #pragma unroll
        for (int m = 0; m < 8; m++) {
            float v = ps[jh * 8 + m][gr];
            __half h = __float2half_rn(v);
            hi[m] = h;
            lo[m] = __float2half_rn(v - __half2float(h));
        }
        uint4 uh, ul;
        uh.x = *(unsigned*)&hi[0]; uh.y = *(unsigned*)&hi[2];
        uh.z = *(unsigned*)&hi[4]; uh.w = *(unsigned*)&hi[6];
        ul.x = *(unsigned*)&lo[0]; ul.y = *(unsigned*)&lo[2];
        ul.z = *(unsigned*)&lo[4]; ul.w = *(unsigned*)&lo[6];
        const int idx = (gr * NN + j0 + jh * 8) / 8;   // uint4 index
        g_PTh[idx] = uh;
        g_PTl[idx] = ul;
    }
}

// ---------------------------------------------------------------------------
// Kernel 2: gate HMMA mainloop (R9 chunk-64 structure) + split-fp16 HMMA
// out-epilogue (replaces the 134M-FFMA fp32 epilogue — the ~10us wall).
//   D[i,j]  = sum_k V[i,k] * U[j,k]                 (K = 512 halfs)
//   S[i,j]  = adj[i,j] * (64 + rowU[j] + rowV[i] + D[i,j])
//   out    += S @ P  via  S_hi@P_hi + S_hi@P_lo + S_lo@P_hi  (fp32 accum)
// smem union (36864 B): mainloop U0|V0|U1|V1 [64][72]h; epilogue S_hi|S_lo
// in regions 0|1, PT_hi|PT_lo in regions 2|3 (two 64-g passes).
// ---------------------------------------------------------------------------
__global__ __launch_bounds__(512, 2) void gate_kernel(const float* __restrict__ adj,
                                                      float* __restrict__ out)
{
    __shared__ __align__(16) char buf[4 * 64 * 72 * 2];   // 36864 B
    __half* base = (__half*)buf;

    const int t    = threadIdx.x;
    const int lane = t & 31, warp = t >> 5;
    const int j0   = blockIdx.x * 64;     // U side (n)
    const int i0   = blockIdx.y * 64;     // V side (m)
    const int wm   = warp >> 2;           // 0..3 -> i offset 16*wm
    const int wn   = warp & 3;            // 0..3 -> j/g offset 16*wn

    const __half* gU = (const __half*)g_U;
    const __half* gV = (const __half*)g_V;

    const int lrow = t >> 3;              // 0..63
    const int lseg = t & 7;               // 0..7

    float d[2][4];
    #pragma unroll
    for (int n = 0; n < 2; n++)
        #pragma unroll
        for (int q = 0; q < 4; q++) d[n][q] = 0.f;

    const uint32_t sBase = smem_u32(base);
    const uint32_t BUFB  = 64 * 72 * 2;   // 9216 B per region
    const uint32_t ldOff = (uint32_t)(lrow * 72 + lseg * 8) * 2;

    // ldmatrix lane offsets within a [64][72]-half region (+ks*32 B per k16)
    const uint32_t aOff = (uint32_t)((16 * wm + (lane & 15)) * 72 + (lane >> 4) * 8) * 2;
    const uint32_t bOff = (uint32_t)((16 * wn + (lane & 15)) * 72 + (lane >> 4) * 8) * 2;

    const __half* uSrc = gU + (j0 + lrow) * 512 + lseg * 8;
    const __half* vSrc = gV + (i0 + lrow) * 512 + lseg * 8;

    // ---- mainloop: 8 chunks of 64 halfs, double buffered ----
    cp_async16(sBase + 0 * BUFB + ldOff, uSrc);
    cp_async16(sBase + 1 * BUFB + ldOff, vSrc);
    cp_commit();

    for (int ch = 0; ch < 8; ch++) {
        const int cur = ch & 1;
        if (ch < 7) {
            const int nxt = cur ^ 1;
            cp_async16(sBase + (nxt * 2 + 0) * BUFB + ldOff, uSrc + (ch + 1) * 64);
            cp_async16(sBase + (nxt * 2 + 1) * BUFB + ldOff, vSrc + (ch + 1) * 64);
            cp_commit();
            asm volatile("cp.async.wait_group 1;");
        } else {
            asm volatile("cp.async.wait_group 0;");
        }
        __syncthreads();

        const uint32_t uB = sBase + (cur * 2 + 0) * BUFB;
        const uint32_t vB = sBase + (cur * 2 + 1) * BUFB;
        #pragma unroll
        for (int ks = 0; ks < 4; ks++) {
            uint32_t a[4], b[4];
            ldsm_x4(a, vB + aOff + ks * 32);
            ldsm_x4(b, uB + bOff + ks * 32);   // non-trans: [n][k] IS the B frag
            mma16816(d[0], a, b[0], b[2]);
            mma16816(d[1], a, b[1], b[3]);
        }
        __syncthreads();
    }

    // ---- scale epilogue: S = adj*(64+rowU+rowV+D), split fp16 -> regions 0|1
    __half* S_hi = base;                  // [64][72]
    __half* S_lo = base + 64 * 72;
    {
        const int r0 = lane >> 2, c0 = (lane & 3) * 2;
        const int ilo = 16 * wm + r0, ihi = ilo + 8;
        const float rvl = g_rowV[i0 + ilo];
        const float rvh = g_rowV[i0 + ihi];
        #pragma unroll
        for (int n = 0; n < 2; n++) {
            const int jc = 16 * wn + 8 * n + c0;
            float2 alo = *(const float2*)&adj[(size_t)(i0 + ilo) * NN + j0 + jc];
            float2 ahi = *(const float2*)&adj[(size_t)(i0 + ihi) * NN + j0 + jc];
            float ru0 = g_rowU[j0 + jc], ru1 = g_rowU[j0 + jc + 1];
            float s00 = alo.x * (64.f + ru0 + rvl + d[n][0]);
            float s01 = alo.y * (64.f + ru1 + rvl + d[n][1]);
            float s10 = ahi.x * (64.f + ru0 + rvh + d[n][2]);
            float s11 = ahi.y * (64.f + ru1 + rvh + d[n][3]);
            __half2 h0 = __floats2half2_rn(s00, s01);
            __half2 h1 = __floats2half2_rn(s10, s11);
            __half2 l0 = __floats2half2_rn(s00 - __half2float(__low2half(h0)),
                                           s01 - __half2float(__high2half(h0)));
            __half2 l1 = __floats2half2_rn(s10 - __half2float(__low2half(h1)),
                                           s11 - __half2float(__high2half(h1)));
            *(__half2*)&S_hi[ilo * 72 + jc] = h0;
            *(__half2*)&S_hi[ihi * 72 + jc] = h1;
            *(__half2*)&S_lo[ilo * 72 + jc] = l0;
            *(__half2*)&S_lo[ihi * 72 + jc] = l1;
        }
    }

    // ---- out epilogue: split-fp16 HMMA, two passes over g-halves ----
    const __half* ptH = (const __half*)g_PTh;
    const __half* ptL = (const __half*)g_PTl;
    const uint32_t sA_hi = sBase + 0 * BUFB + aOff;
    const uint32_t sA_lo = sBase + 1 * BUFB + aOff;
    const uint32_t sB_hi = sBase + 2 * BUFB + bOff;
    const uint32_t sB_lo = sBase + 3 * BUFB + bOff;
    const uint32_t ptDstH = sBase + 2 * BUFB + ldOff;
    const uint32_t ptDstL = sBase + 3 * BUFB + ldOff;

    #pragma unroll
    for (int pass = 0; pass < 2; pass++) {
        __syncthreads();   // pass0: S stores + mainloop reads of regions 2|3
                           // pass1: previous PT reads complete
        cp_async16(ptDstH, ptH + (pass * 64 + lrow) * NN + j0 + lseg * 8);
        cp_async16(ptDstL, ptL + (pass * 64 + lrow) * NN + j0 + lseg * 8);
        cp_commit();
        asm volatile("cp.async.wait_group 0;");
        __syncthreads();

        float e[2][4];
        #pragma unroll
        for (int n = 0; n < 2; n++)
            #pragma unroll
            for (int q = 0; q < 4; q++) e[n][q] = 0.f;

        #pragma unroll
        for (int ks = 0; ks < 4; ks++) {
            uint32_t ah[4], al[4], bh[4], bl[4];
            ldsm_x4(ah, sA_hi + ks * 32);
            ldsm_x4(al, sA_lo + ks * 32);
            ldsm_x4(bh, sB_hi + ks * 32);
            ldsm_x4(bl, sB_lo + ks * 32);
            mma16816(e[0], ah, bh[0], bh[2]);   // hi*hi
            mma16816(e[1], ah, bh[1], bh[3]);
            mma16816(e[0], ah, bl[0], bl[2]);   // hi*lo
            mma16816(e[1], ah, bl[1], bl[3]);
            mma16816(e[0], al, bh[0], bh[2]);   // lo*hi
            mma16816(e[1], al, bh[1], bh[3]);
        }

        const int r0 = lane >> 2, c0 = (lane & 3) * 2;
        const int iL = i0 + 16 * wm + r0, iH = iL + 8;
        #pragma unroll
        for (int n = 0; n < 2; n++) {
            const int g = pass * 64 + 16 * wn + 8 * n + c0;
            atomicAdd(&out[iL * FF + g    ], e[n][0]);
            atomicAdd(&out[iL * FF + g + 1], e[n][1]);
            atomicAdd(&out[iH * FF + g    ], e[n][2]);
            atomicAdd(&out[iH * FF + g + 1], e[n][3]);
        }
    }
}

// ---------------------------------------------------------------------------
extern "C" void kernel_launch(void* const* d_in, const int* in_sizes, int n_in,
                              void* d_out, int out_size)
{
    const float* input   = (const float*)d_in[0];   // [1024,128]
    const float* adj     = (const float*)d_in[1];   // [1024,1024]
    // d_in[2] = feat_adj : unused by the reference
    const float* weight  = (const float*)d_in[3];   // [128,128]
    const float* bias    = (const float*)d_in[4];   // [128]
    const float* w1      = (const float*)d_in[5];   // [128,256]
    const float* b1      = (const float*)d_in[6];   // [128]
    float* out = (float*)d_out;                     // [1024,128]

    prep_kernel<<<dim3(256, 4), 256>>>(input, w1, b1, weight, bias, out);
    gate_kernel<<<dim3(16, 16), 512>>>(adj, out);
}

// round 12
// speedup vs baseline: 1.2770x; 1.0084x over previous
#include <cuda_runtime.h>
#include <cuda_fp16.h>
#include <cstdint>

#define NN 1024
#define FF 128

// Scratch (allocation-free rule: __device__ globals)
__device__ unsigned g_U[NN * 256];       // fp16 (u1,u2),(u3,u4) per f -> K=512  [j,k]
__device__ unsigned g_V[NN * 256];       // fp16 (b,b^2),(b^3,b^4) per f         [i,k]
__device__ float    g_rowU[NN];          // sum_f (c1 a + c3 a^3 + c5 a^5)       [j]
__device__ float    g_rowV[NN];          // sum_f  c5 b^5                        [i]
__device__ uint4    g_PTh[FF * NN / 8];  // fp16 hi of P^T   [g][j]  (128 x 1024)
__device__ uint4    g_PTl[FF * NN / 8];  // fp16 lo residual [g][j]

// sigmoid(x) = 0.5 + c1 x + c3 x^3 + c5 x^5  (|x| <~ 1)
#define C1 0.25f
#define C3 (-0.020833333f)
#define C5 0.0020833333f

__device__ __forceinline__ uint32_t smem_u32(const void* p) {
    return (uint32_t)__cvta_generic_to_shared(p);
}
__device__ __forceinline__ void ldsm_x4(uint32_t* r, uint32_t a) {
    asm volatile("ldmatrix.sync.aligned.m8n8.x4.shared.b16 {%0,%1,%2,%3}, [%4];"
        : "=r"(r[0]), "=r"(r[1]), "=r"(r[2]), "=r"(r[3]) : "r"(a));
}
__device__ __forceinline__ void mma16816(float* d, const uint32_t* a,
                                         uint32_t b0, uint32_t b1) {
    asm volatile("mma.sync.aligned.m16n8k16.row.col.f32.f16.f16.f32 "
        "{%0,%1,%2,%3},{%4,%5,%6,%7},{%8,%9},{%0,%1,%2,%3};"
        : "+f"(d[0]), "+f"(d[1]), "+f"(d[2]), "+f"(d[3])
        : "r"(a[0]), "r"(a[1]), "r"(a[2]), "r"(a[3]), "r"(b0), "r"(b1));
}
__device__ __forceinline__ void cp_async16(uint32_t dst, const void* src) {
    asm volatile("cp.async.cg.shared.global [%0], [%1], 16;" :: "r"(dst), "l"(src));
}
__device__ __forceinline__ void cp_commit() {
    asm volatile("cp.async.commit_group;");
}

// ---------------------------------------------------------------------------
// Kernel 1: prep (identical to R11 — verified). grid (256, 4), block 256.
// ---------------------------------------------------------------------------
__global__ __launch_bounds__(256) void prep_kernel(
        const float* __restrict__ input,
        const float* __restrict__ w1,
        const float* __restrict__ b1,
        const float* __restrict__ weight,
        const float* __restrict__ bias,
        float* __restrict__ out)
{
    const int mat = blockIdx.y;
    const int t   = threadIdx.x;
    const int col = t & 127;
    const int rh  = t >> 7;          // 0..1

    if (mat == 3) {
        const int j0 = blockIdx.x * 4;
        const float bv = bias[col];
        out[(j0 + rh * 2 + 0) * FF + col] = bv;
        out[(j0 + rh * 2 + 1) * FF + col] = bv;
        return;
    }
    if (blockIdx.x >= 64) return;
    const int j0 = blockIdx.x * 16;       // 16 rows/block

    __shared__ float in_s[16][FF];        // 8 KB
    __shared__ float w_s[32][133];        // 17 KB (w1 chunk / P-transpose stage)
    __shared__ float red[16][4];

    for (int idx = t; idx < 16 * FF; idx += 256)
        in_s[idx >> 7][idx & 127] = input[(j0 + (idx >> 7)) * FF + (idx & 127)];

    float acc[8];
    #pragma unroll
    for (int r = 0; r < 8; r++) acc[r] = 0.f;

    if (mat < 2) {
        const int off = mat ? 128 : 0;
        const int lk = t & 31, lf = t >> 5;   // chunk load map
        float pre[16];
        #pragma unroll
        for (int i = 0; i < 16; i++)          // prefetch chunk 0
            pre[i] = w1[(lf + i * 8) * 256 + off + lk];

        for (int ch = 0; ch < 4; ch++) {
            #pragma unroll
            for (int i = 0; i < 16; i++)
                w_s[lk][lf + i * 8] = pre[i];
            __syncthreads();
            if (ch < 3) {
                #pragma unroll
                for (int i = 0; i < 16; i++)  // prefetch next chunk (hidden)
                    pre[i] = w1[(lf + i * 8) * 256 + off + (ch + 1) * 32 + lk];
            }
            const int k0 = ch * 32;
            #pragma unroll
            for (int k4 = 0; k4 < 8; k4++) {
                const int k = k4 * 4;
                float w0 = w_s[k + 0][col];
                float w1v = w_s[k + 1][col];
                float w2 = w_s[k + 2][col];
                float w3 = w_s[k + 3][col];
                #pragma unroll
                for (int r = 0; r < 8; r++) {
                    float4 iv = *(const float4*)&in_s[rh * 8 + r][k0 + k];
                    acc[r] += iv.x * w0;
                    acc[r] += iv.y * w1v;
                    acc[r] += iv.z * w2;
                    acc[r] += iv.w * w3;
                }
            }
            __syncthreads();   // compute done before next chunk's STS
        }

        float rsum[8];
        if (mat == 0) {
            #pragma unroll
            for (int r = 0; r < 8; r++) {
                float a = acc[r], a2 = a * a, a4 = a2 * a2;
                float u1 = C1 + 3.f * C3 * a2 + 5.f * C5 * a4;
                float u2 = a * (3.f * C3 + 10.f * C5 * a2);
                float u3 = C3 + 10.f * C5 * a2;
                float u4 = 5.f * C5 * a;
                rsum[r] = a * (C1 + a2 * (C3 + C5 * a2));   // rowU term
                __half2 h01 = __floats2half2_rn(u1, u2);
                __half2 h23 = __floats2half2_rn(u3, u4);
                *(uint2*)&g_U[(j0 + rh * 8 + r) * 256 + col * 2] =
                    make_uint2(*(unsigned*)&h01, *(unsigned*)&h23);
            }
        } else {
            const float bb = b1[col];
            #pragma unroll
            for (int r = 0; r < 8; r++) {
                float b = acc[r] + bb;
                float b2 = b * b;
                rsum[r] = C5 * b * b2 * b2;                 // rowV term (b^5)
                __half2 h01 = __floats2half2_rn(b, b2);
                __half2 h23 = __floats2half2_rn(b * b2, b2 * b2);
                *(uint2*)&g_V[(j0 + rh * 8 + r) * 256 + col * 2] =
                    make_uint2(*(unsigned*)&h01, *(unsigned*)&h23);
            }
        }
        // reduce rsum over f
        #pragma unroll
        for (int r = 0; r < 8; r++)
            #pragma unroll
            for (int o = 16; o; o >>= 1)
                rsum[r] += __shfl_xor_sync(0xffffffffu, rsum[r], o);
        if ((t & 31) == 0) {
            const int w = t >> 5;
            #pragma unroll
            for (int r = 0; r < 8; r++)
                red[(w >> 2) * 8 + r][w & 3] = rsum[r];
        }
        __syncthreads();
        if (t < 16) {
            float v = red[t][0] + red[t][1] + red[t][2] + red[t][3];
            if (mat == 0) g_rowU[j0 + t] = v; else g_rowV[j0 + t] = v;
        }
        return;
    }

    // mat == 2: P rows j0..j0+15 -> transposed split-fp16 PT[g][j]
    __syncthreads();
    #pragma unroll 4
    for (int k4 = 0; k4 < 32; k4++) {
        const int k = k4 * 4;
        float w0 = weight[(k + 0) * FF + col];
        float w1v = weight[(k + 1) * FF + col];
        float w2 = weight[(k + 2) * FF + col];
        float w3 = weight[(k + 3) * FF + col];
        #pragma unroll
        for (int r = 0; r < 8; r++) {
            float4 iv = *(const float4*)&in_s[rh * 8 + r][k];
            acc[r] += iv.x * w0;
            acc[r] += iv.y * w1v;
            acc[r] += iv.z * w2;
            acc[r] += iv.w * w3;
        }
    }
    // stage [16 j][128 g] f32 in smem, then write transposed 8-half runs
    float (*ps)[133] = (float(*)[133])w_s;    // reuse; [16][133] fits [32][133]
    #pragma unroll
    for (int r = 0; r < 8; r++) ps[rh * 8 + r][col] = acc[r];
    __syncthreads();

    {
        const int gr = t >> 1;        // 0..127 : g row
        const int jh = t & 1;         // 0..1   : j half (8 each)
        __half hi[8], lo[8];
        #pragma unroll
        for (int m = 0; m < 8; m++) {
            float v = ps[jh * 8 + m][gr];
            __half h = __float2half_rn(v);
            hi[m] = h;
            lo[m] = __float2half_rn(v - __half2float(h));
        }
        uint4 uh, ul;
        uh.x = *(unsigned*)&hi[0]; uh.y = *(unsigned*)&hi[2];
        uh.z = *(unsigned*)&hi[4]; uh.w = *(unsigned*)&hi[6];
        ul.x = *(unsigned*)&lo[0]; ul.y = *(unsigned*)&lo[2];
        ul.z = *(unsigned*)&lo[4]; ul.w = *(unsigned*)&lo[6];
        const int idx = (gr * NN + j0 + jh * 8) / 8;   // uint4 index
        g_PTh[idx] = uh;
        g_PTl[idx] = ul;
    }
}

// ---------------------------------------------------------------------------
// Kernel 2: gate HMMA + split-fp16 HMMA out-epilogue.
// NEW (R12): 3-stage chunk-64 ring over 6 smem regions (55.3 KB dynamic):
//   - ONE __syncthreads per chunk (the sync that publishes chunk ch also
//     retires all reads of the stage being overwritten) -> 8 mainloop syncs.
//   - PT pass-0/pass-1 tiles prefetched into ring slots freed at chunks 6/7
//     -> epilogue has ZERO exposed loads and no inter-pass syncs.
// Region map: mainloop stage s: U->r(2s), V->r(2s+1).  Epilogue: S_hi->r2,
// S_lo->r3, PT0 hi/lo->r4/r5, PT1 hi/lo->r0/r1.
// ---------------------------------------------------------------------------
__global__ __launch_bounds__(512, 2) void gate_kernel(const float* __restrict__ adj,
                                                      float* __restrict__ out)
{
    extern __shared__ __align__(16) char buf[];       // 6 * 9216 = 55296 B
    __half* base = (__half*)buf;

    const int t    = threadIdx.x;
    const int lane = t & 31, warp = t >> 5;
    const int j0   = blockIdx.x * 64;     // U side (n)
    const int i0   = blockIdx.y * 64;     // V side (m)
    const int wm   = warp >> 2;           // 0..3 -> i offset 16*wm
    const int wn   = warp & 3;            // 0..3 -> j/g offset 16*wn

    const __half* gU = (const __half*)g_U;
    const __half* gV = (const __half*)g_V;
    const __half* ptH = (const __half*)g_PTh;
    const __half* ptL = (const __half*)g_PTl;

    const int lrow = t >> 3;              // 0..63
    const int lseg = t & 7;               // 0..7

    float d[2][4];
    #pragma unroll
    for (int n = 0; n < 2; n++)
        #pragma unroll
        for (int q = 0; q < 4; q++) d[n][q] = 0.f;

    const uint32_t sBase = smem_u32(base);
    const uint32_t BUFB  = 64 * 72 * 2;   // 9216 B per region
    const uint32_t ldOff = (uint32_t)(lrow * 72 + lseg * 8) * 2;

    const uint32_t aOff = (uint32_t)((16 * wm + (lane & 15)) * 72 + (lane >> 4) * 8) * 2;
    const uint32_t bOff = (uint32_t)((16 * wn + (lane & 15)) * 72 + (lane >> 4) * 8) * 2;

    const __half* uSrc = gU + (j0 + lrow) * 512 + lseg * 8;
    const __half* vSrc = gV + (i0 + lrow) * 512 + lseg * 8;
    const __half* pHsrc = ptH + lrow * NN + j0 + lseg * 8;   // pass0 rows g=lrow
    const __half* pLsrc = ptL + lrow * NN + j0 + lseg * 8;

    // prologue: chunks 0,1 -> stages 0,1
    cp_async16(sBase + 0 * BUFB + ldOff, uSrc);
    cp_async16(sBase + 1 * BUFB + ldOff, vSrc);
    cp_commit();
    cp_async16(sBase + 2 * BUFB + ldOff, uSrc + 64);
    cp_async16(sBase + 3 * BUFB + ldOff, vSrc + 64);
    cp_commit();

    #pragma unroll 1
    for (int ch = 0; ch < 8; ch++) {
        asm volatile("cp.async.wait_group 1;");   // chunk ch arrived (FIFO)
        __syncthreads();                          // + stage (ch+2)%3 reads done
        if (ch < 6) {
            const int st = (ch + 2) % 3;
            cp_async16(sBase + (2 * st + 0) * BUFB + ldOff, uSrc + (ch + 2) * 64);
            cp_async16(sBase + (2 * st + 1) * BUFB + ldOff, vSrc + (ch + 2) * 64);
            cp_commit();
        } else if (ch == 6) {                     // stage2 (r4,r5) freed -> PT0
            cp_async16(sBase + 4 * BUFB + ldOff, pHsrc);
            cp_async16(sBase + 5 * BUFB + ldOff, pLsrc);
            cp_commit();
        } else {                                  // stage0 (r0,r1) freed -> PT1
            cp_async16(sBase + 0 * BUFB + ldOff, pHsrc + 64 * NN);
            cp_async16(sBase + 1 * BUFB + ldOff, pLsrc + 64 * NN);
            cp_commit();
        }
        const int st = ch % 3;
        const uint32_t uB = sBase + (2 * st + 0) * BUFB;
        const uint32_t vB = sBase + (2 * st + 1) * BUFB;
        #pragma unroll
        for (int ks = 0; ks < 4; ks++) {
            uint32_t a[4], b[4];
            ldsm_x4(a, vB + aOff + ks * 32);
            ldsm_x4(b, uB + bOff + ks * 32);   // non-trans: [n][k] IS the B frag
            mma16816(d[0], a, b[0], b[2]);
            mma16816(d[1], a, b[1], b[3]);
        }
    }

    asm volatile("cp.async.wait_group 0;");   // PT0 + PT1 resident
    __syncthreads();                          // mainloop reads of r2,r3 retired

    // scale epilogue: S = adj*(64+rowU+rowV+D), split fp16 -> r2 (hi), r3 (lo)
    __half* S_hi = base + 2 * 64 * 72;
    __half* S_lo = base + 3 * 64 * 72;
    {
        const int r0 = lane >> 2, c0 = (lane & 3) * 2;
        const int ilo = 16 * wm + r0, ihi = ilo + 8;
        const float rvl = g_rowV[i0 + ilo];
        const float rvh = g_rowV[i0 + ihi];
        #pragma unroll
        for (int n = 0; n < 2; n++) {
            const int jc = 16 * wn + 8 * n + c0;
            float2 alo = *(const float2*)&adj[(size_t)(i0 + ilo) * NN + j0 + jc];
            float2 ahi = *(const float2*)&adj[(size_t)(i0 + ihi) * NN + j0 + jc];
            float ru0 = g_rowU[j0 + jc], ru1 = g_rowU[j0 + jc + 1];
            float s00 = alo.x * (64.f + ru0 + rvl + d[n][0]);
            float s01 = alo.y * (64.f + ru1 + rvl + d[n][1]);
            float s10 = ahi.x * (64.f + ru0 + rvh + d[n][2]);
            float s11 = ahi.y * (64.f + ru1 + rvh + d[n][3]);
            __half2 h0 = __floats2half2_rn(s00, s01);
            __half2 h1 = __floats2half2_rn(s10, s11);
            __half2 l0 = __floats2half2_rn(s00 - __half2float(__low2half(h0)),
                                           s01 - __half2float(__high2half(h0)));
            __half2 l1 = __floats2half2_rn(s10 - __half2float(__low2half(h1)),
                                           s11 - __half2float(__high2half(h1)));
            *(__half2*)&S_hi[ilo * 72 + jc] = h0;
            *(__half2*)&S_hi[ihi * 72 + jc] = h1;
            *(__half2*)&S_lo[ilo * 72 + jc] = l0;
            *(__half2*)&S_lo[ihi * 72 + jc] = l1;
        }
    }
    __syncthreads();

    // out epilogue: two g-passes, everything already in smem, no more syncs.
    const uint32_t sA_hi = sBase + 2 * BUFB + aOff;
    const uint32_t sA_lo = sBase + 3 * BUFB + aOff;

    #pragma unroll
    for (int pass = 0; pass < 2; pass++) {
        const uint32_t sB_hi = sBase + (pass ? 0 : 4) * BUFB + bOff;
        const uint32_t sB_lo = sBase + (pass ? 1 : 5) * BUFB + bOff;

        float e[2][4];
        #pragma unroll
        for (int n = 0; n < 2; n++)
            #pragma unroll
            for (int q = 0; q < 4; q++) e[n][q] = 0.f;

        #pragma unroll
        for (int ks = 0; ks < 4; ks++) {
            uint32_t ah[4], al[4], bh[4], bl[4];
            ldsm_x4(ah, sA_hi + ks * 32);
            ldsm_x4(al, sA_lo + ks * 32);
            ldsm_x4(bh, sB_hi + ks * 32);
            ldsm_x4(bl, sB_lo + ks * 32);
            mma16816(e[0], ah, bh[0], bh[2]);   // hi*hi
            mma16816(e[1], ah, bh[1], bh[3]);
            mma16816(e[0], ah, bl[0], bl[2]);   // hi*lo
            mma16816(e[1], ah, bl[1], bl[3]);
            mma16816(e[0], al, bh[0], bh[2]);   // lo*hi
            mma16816(e[1], al, bh[1], bh[3]);
        }

        const int r0 = lane >> 2, c0 = (lane & 3) * 2;
        const int iL = i0 + 16 * wm + r0, iH = iL + 8;
        #pragma unroll
        for (int n = 0; n < 2; n++) {
            const int g = pass * 64 + 16 * wn + 8 * n + c0;
            atomicAdd(&out[iL * FF + g    ], e[n][0]);
            atomicAdd(&out[iL * FF + g + 1], e[n][1]);
            atomicAdd(&out[iH * FF + g    ], e[n][2]);
            atomicAdd(&out[iH * FF + g + 1], e[n][3]);
        }
    }
}

// ---------------------------------------------------------------------------
extern "C" void kernel_launch(void* const* d_in, const int* in_sizes, int n_in,
                              void* d_out, int out_size)
{
    const float* input   = (const float*)d_in[0];   // [1024,128]
    const float* adj     = (const float*)d_in[1];   // [1024,1024]
    // d_in[2] = feat_adj : unused by the reference
    const float* weight  = (const float*)d_in[3];   // [128,128]
    const float* bias    = (const float*)d_in[4];   // [128]
    const float* w1      = (const float*)d_in[5];   // [128,256]
    const float* b1      = (const float*)d_in[6];   // [128]
    float* out = (float*)d_out;                     // [1024,128]

    const int GATE_SMEM = 6 * 64 * 72 * 2;          // 55296 B
    cudaFuncSetAttribute(gate_kernel,
                         cudaFuncAttributeMaxDynamicSharedMemorySize, GATE_SMEM);

    prep_kernel<<<dim3(256, 4), 256>>>(input, w1, b1, weight, bias, out);
    gate_kernel<<<dim3(16, 16), 512, GATE_SMEM>>>(adj, out);
}